// round 7
// baseline (speedup 1.0000x reference)
#include <cuda_runtime.h>

typedef unsigned long long u64;

#define SEQ   256
#define LAB   128
#define BATCH 8192
#define NF    8
#define HD    64
#define G3    192
#define NTHR  256          // 8 warps: 4 row-groups x 2 unit-halves
#define TB    32           // rows per block (4 groups x 8 rows)
#define NBLK  (BATCH / TB) // 256
#define HS    12           // h_T k-row stride (floats): 48B, 16B-aligned

// ---- SMEM layout (float offsets) ----
#define OFF_WIH  0                       // [8 k][192]  (gate*64 + unit)
#define OFF_WHH  1536                    // [64 k][192]
#define OFF_BIAS 13824                   // [4][64] : r, z, n_i, n_h
#define OFF_WOUT 14080                   // [64 k][4 o][2] pairs (Wout[o][k],Wout[o+4][k])
#define OFF_BOUT 14592                   // [4][2]
#define OFF_HT   14608                   // [4 g][2 buf][64 k][HS]
#define OFF_XT   (OFF_HT + 4*2*64*HS)    // [4 g][2 buf][8 feat][8 row]
#define SMEM_FLOATS (OFF_XT + 4*2*64)
#define SMEM_BYTES  (SMEM_FLOATS * 4)

__device__ __forceinline__ u64 f2fma(u64 a, u64 b, u64 c) {
    u64 d; asm("fma.rn.f32x2 %0,%1,%2,%3;" : "=l"(d) : "l"(a), "l"(b), "l"(c)); return d;
}
__device__ __forceinline__ u64 dup2(float v) {
    u64 d; asm("mov.b64 %0,{%1,%1};" : "=l"(d) : "f"(v)); return d;
}
__device__ __forceinline__ u64 pack2(float a, float b) {
    u64 d; asm("mov.b64 %0,{%1,%2};" : "=l"(d) : "f"(a), "f"(b)); return d;
}
__device__ __forceinline__ void unpk(u64 v, float& a, float& b) {
    asm("mov.b64 {%0,%1},%2;" : "=f"(a), "=f"(b) : "l"(v));
}
__device__ __forceinline__ float tanha(float x) {
    float y; asm("tanh.approx.f32 %0,%1;" : "=f"(y) : "f"(x)); return y;
}
__device__ __forceinline__ float sigt(float x) { return fmaf(0.5f, tanha(0.5f * x), 0.5f); }
__device__ __forceinline__ void pair_bar(int g) {
    asm volatile("bar.sync %0, 64;" :: "r"(1 + g) : "memory");
}

// One GRU step: warp handles 8 rows x 32 units (its half). Rows packed in f32x2.
__device__ __forceinline__ void gru_step(
    const float* __restrict__ wih,   // [8][192]
    const float* __restrict__ whh,   // [64][192]
    u64 br, u64 bz, u64 bni, u64 bnh,
    const float* __restrict__ xt,    // x_T[feat][8 rows]
    const float* __restrict__ hc,    // h_T cur  [k][HS]
    float*       __restrict__ hn,    // h_T next [k][HS]
    float hr[8],                     // this lane's unit: old h for 8 rows (regs)
    int u)
{
    u64 Ar[4], Az[4], An[4], Ah[4];
    #pragma unroll
    for (int rp = 0; rp < 4; rp++) { Ar[rp] = br; Az[rp] = bz; An[rp] = bni; Ah[rp] = bnh; }

    // ---- input GEMM (k = 0..7) ----
    #pragma unroll
    for (int kf = 0; kf < NF; kf++) {
        const float* w = wih + kf * G3 + u;
        u64 wr = dup2(w[0]), wz = dup2(w[64]), wn = dup2(w[128]);
        ulonglong2 x01 = *(const ulonglong2*)(xt + kf * 8);
        ulonglong2 x23 = *(const ulonglong2*)(xt + kf * 8 + 4);
        u64 xp0 = x01.x, xp1 = x01.y, xp2 = x23.x, xp3 = x23.y;
        Ar[0] = f2fma(xp0, wr, Ar[0]); Az[0] = f2fma(xp0, wz, Az[0]); An[0] = f2fma(xp0, wn, An[0]);
        Ar[1] = f2fma(xp1, wr, Ar[1]); Az[1] = f2fma(xp1, wz, Az[1]); An[1] = f2fma(xp1, wn, An[1]);
        Ar[2] = f2fma(xp2, wr, Ar[2]); Az[2] = f2fma(xp2, wz, Az[2]); An[2] = f2fma(xp2, wn, An[2]);
        Ar[3] = f2fma(xp3, wr, Ar[3]); Az[3] = f2fma(xp3, wz, Az[3]); An[3] = f2fma(xp3, wn, An[3]);
    }

    // ---- recurrent GEMM (k = 0..63) ----
    #pragma unroll 4
    for (int k = 0; k < HD; k++) {
        const float* w = whh + k * G3 + u;
        u64 wr = dup2(w[0]), wz = dup2(w[64]), wn = dup2(w[128]);
        ulonglong2 h01 = *(const ulonglong2*)(hc + k * HS);
        ulonglong2 h23 = *(const ulonglong2*)(hc + k * HS + 4);
        u64 hp0 = h01.x, hp1 = h01.y, hp2 = h23.x, hp3 = h23.y;
        Ar[0] = f2fma(hp0, wr, Ar[0]); Az[0] = f2fma(hp0, wz, Az[0]); Ah[0] = f2fma(hp0, wn, Ah[0]);
        Ar[1] = f2fma(hp1, wr, Ar[1]); Az[1] = f2fma(hp1, wz, Az[1]); Ah[1] = f2fma(hp1, wn, Ah[1]);
        Ar[2] = f2fma(hp2, wr, Ar[2]); Az[2] = f2fma(hp2, wz, Az[2]); Ah[2] = f2fma(hp2, wn, Ah[2]);
        Ar[3] = f2fma(hp3, wr, Ar[3]); Az[3] = f2fma(hp3, wz, Az[3]); Ah[3] = f2fma(hp3, wn, Ah[3]);
    }

    // ---- gates + h update (lane owns unit u, 8 rows; old h in regs) ----
    #pragma unroll
    for (int rp = 0; rp < 4; rp++) {
        float r0, r1, z0, z1, i0, i1, g0, g1;
        unpk(Ar[rp], r0, r1); unpk(Az[rp], z0, z1);
        unpk(An[rp], i0, i1); unpk(Ah[rp], g0, g1);
        float R0 = sigt(r0), R1 = sigt(r1);
        float Z0 = sigt(z0), Z1 = sigt(z1);
        float N0 = tanha(fmaf(R0, g0, i0));
        float N1 = tanha(fmaf(R1, g1, i1));
        hr[2 * rp]     = fmaf(Z0, hr[2 * rp]     - N0, N0);
        hr[2 * rp + 1] = fmaf(Z1, hr[2 * rp + 1] - N1, N1);
    }
    // write h_T[u][0..7] (scalars; read next step as row-pairs)
    ulonglong2 s0, s1;
    s0.x = pack2(hr[0], hr[1]); s0.y = pack2(hr[2], hr[3]);
    s1.x = pack2(hr[4], hr[5]); s1.y = pack2(hr[6], hr[7]);
    *(ulonglong2*)(hn + u * HS)     = s0;
    *(ulonglong2*)(hn + u * HS + 4) = s1;
}

__device__ __forceinline__ void load_weights(
    float* smem,
    const float* __restrict__ Wih, const float* __restrict__ Whh,
    const float* __restrict__ bih, const float* __restrict__ bhh, int tid)
{
    for (int i = tid; i < NF * G3; i += NTHR) {          // wih[k][j] = Wih[j][k]
        int k = i / G3, j = i % G3;
        smem[OFF_WIH + i] = Wih[j * NF + k];
    }
    for (int i = tid; i < HD * G3; i += NTHR) {
        int k = i / G3, j = i % G3;
        smem[OFF_WHH + i] = Whh[j * HD + k];
    }
    if (tid < HD) {
        smem[OFF_BIAS + tid]       = bih[tid]       + bhh[tid];
        smem[OFF_BIAS + 64 + tid]  = bih[64 + tid]  + bhh[64 + tid];
        smem[OFF_BIAS + 128 + tid] = bih[128 + tid];
        smem[OFF_BIAS + 192 + tid] = bhh[128 + tid];
    }
}

__global__ __launch_bounds__(NTHR, 2)
void seq2seq_gru_kernel(const float* __restrict__ x,
                        const float* __restrict__ xy,
                        const float* __restrict__ eWih, const float* __restrict__ eWhh,
                        const float* __restrict__ ebih, const float* __restrict__ ebhh,
                        const float* __restrict__ dWih, const float* __restrict__ dWhh,
                        const float* __restrict__ dbih, const float* __restrict__ dbhh,
                        const float* __restrict__ Wout, const float* __restrict__ bout,
                        float* __restrict__ out)
{
    extern __shared__ float smem[];
    const int tid  = threadIdx.x;
    const int lane = tid & 31;
    const int warp = tid >> 5;
    const int g    = warp >> 1;          // row group 0..3
    const int uh   = warp & 1;           // unit half
    const int u    = uh * 32 + lane;     // this lane's unit 0..63
    const int rowb = blockIdx.x * TB + g * 8;

    const float* wih = smem + OFF_WIH;
    const float* whh = smem + OFF_WHH;
    float* ht = smem + OFF_HT + g * (2 * 64 * HS);   // + buf*768
    float* xt = smem + OFF_XT + g * 128;             // + buf*64

    // ---- init: encoder weights, out-proj, zero h, stage x[0] ----
    load_weights(smem, eWih, eWhh, ebih, ebhh, tid);
    for (int i = tid; i < HD * 8; i += NTHR) {       // wout pairs
        int k = i >> 3, rem = i & 7, o = rem >> 1, s = rem & 1;
        smem[OFF_WOUT + i] = Wout[(o + 4 * s) * HD + k];
    }
    if (tid < 8) { int o = tid >> 1, s = tid & 1; smem[OFF_BOUT + tid] = bout[o + 4 * s]; }
    for (int i = tid; i < 4 * 2 * 64 * HS; i += NTHR) smem[OFF_HT + i] = 0.0f;
    if (uh == 0 && lane < 16) {                      // stage x[0] transposed into buf0
        float4 v = ((const float4*)(x + (size_t)rowb * NF))[lane];
        int i0 = lane * 4;
        xt[((i0 + 0) & 7) * 8 + ((i0 + 0) >> 3)] = v.x;
        xt[((i0 + 1) & 7) * 8 + ((i0 + 1) >> 3)] = v.y;
        xt[((i0 + 2) & 7) * 8 + ((i0 + 2) >> 3)] = v.z;
        xt[((i0 + 3) & 7) * 8 + ((i0 + 3) >> 3)] = v.w;
    }
    __syncthreads();

    float hr[8];
    #pragma unroll
    for (int r = 0; r < 8; r++) hr[r] = 0.0f;

    u64 br  = dup2(smem[OFF_BIAS + u]);
    u64 bz  = dup2(smem[OFF_BIAS + 64 + u]);
    u64 bni = dup2(smem[OFF_BIAS + 128 + u]);
    u64 bnh = dup2(smem[OFF_BIAS + 192 + u]);

    // =========================== ENCODER ===========================
    for (int t = 0; t < SEQ; t++) {
        const bool st = (uh == 0) && (lane < 16) && (t + 1 < SEQ);
        float4 nx;
        if (st) nx = ((const float4*)(x + ((size_t)(t + 1) * BATCH + rowb) * NF))[lane];
        gru_step(wih, whh, br, bz, bni, bnh,
                 xt + (t & 1) * 64,
                 ht + (t & 1) * 768, ht + ((t + 1) & 1) * 768,
                 hr, u);
        if (st) {
            float* xn = xt + ((t + 1) & 1) * 64;
            int i0 = lane * 4;
            xn[((i0 + 0) & 7) * 8 + ((i0 + 0) >> 3)] = nx.x;
            xn[((i0 + 1) & 7) * 8 + ((i0 + 1) >> 3)] = nx.y;
            xn[((i0 + 2) & 7) * 8 + ((i0 + 2) >> 3)] = nx.z;
            xn[((i0 + 3) & 7) * 8 + ((i0 + 3) >> 3)] = nx.w;
        }
        pair_bar(g);   // h(next) + x(next) visible to partner warp
    }

    // ---- phase swap: decoder weights, stage xy[0] ----
    __syncthreads();
    load_weights(smem, dWih, dWhh, dbih, dbhh, tid);
    if (uh == 0 && lane < 16) {                      // stage xy[0] into buf0
        float4 v = ((const float4*)(xy + (size_t)rowb * NF))[lane];
        int i0 = lane * 4;
        xt[((i0 + 0) & 7) * 8 + ((i0 + 0) >> 3)] = v.x;
        xt[((i0 + 1) & 7) * 8 + ((i0 + 1) >> 3)] = v.y;
        xt[((i0 + 2) & 7) * 8 + ((i0 + 2) >> 3)] = v.z;
        xt[((i0 + 3) & 7) * 8 + ((i0 + 3) >> 3)] = v.w;
    }
    __syncthreads();

    br  = dup2(smem[OFF_BIAS + u]);
    bz  = dup2(smem[OFF_BIAS + 64 + u]);
    bni = dup2(smem[OFF_BIAS + 128 + u]);
    bnh = dup2(smem[OFF_BIAS + 192 + u]);

    // =========================== DECODER ===========================
    // out-proj: lanes 0..15: row = lane>>1, o2 = lane&1 -> o = uh*2 + o2 (and o+4)
    const int orow = lane >> 1;
    const int oo   = uh * 2 + (lane & 1);
    const u64 bop  = ((const u64*)(smem + OFF_BOUT))[oo];
    const u64* woutq = (const u64*)(smem + OFF_WOUT) + oo;   // stride 4 u64 per k

    for (int t = 0; t < LAB; t++) {
        gru_step(wih, whh, br, bz, bni, bnh,
                 xt + (t & 1) * 64,
                 ht + (t & 1) * 768, ht + ((t + 1) & 1) * 768,
                 hr, u);
        pair_bar(g);   // full h(next) visible

        if (lane < 16) {
            const float* hn = ht + ((t + 1) & 1) * 768;
            u64 acc = bop;
            #pragma unroll 8
            for (int k = 0; k < HD; k++)
                acc = f2fma(dup2(hn[k * HS + orow]), woutq[k * 4], acc);
            float oa, ob; unpk(acc, oa, ob);

            float* og = out + ((size_t)t * BATCH + rowb + orow) * NF;
            og[oo]     = oa;
            og[oo + 4] = ob;

            if (t + 1 < LAB) {
                float* xn = xt + ((t + 1) & 1) * 64;
                xn[oo * 8 + orow]       = oa;
                xn[(oo + 4) * 8 + orow] = ob;
            }
        }
        pair_bar(g);   // feedback x(next) visible
    }
}

extern "C" void kernel_launch(void* const* d_in, const int* in_sizes, int n_in,
                              void* d_out, int out_size) {
    (void)in_sizes; (void)n_in; (void)out_size;
    const float* x     = (const float*)d_in[0];
    const float* xy    = (const float*)d_in[1];
    const float* eWih  = (const float*)d_in[2];
    const float* eWhh  = (const float*)d_in[3];
    const float* ebih  = (const float*)d_in[4];
    const float* ebhh  = (const float*)d_in[5];
    const float* dWih  = (const float*)d_in[6];
    const float* dWhh  = (const float*)d_in[7];
    const float* dbih  = (const float*)d_in[8];
    const float* dbhh  = (const float*)d_in[9];
    const float* Wout  = (const float*)d_in[10];
    const float* bout  = (const float*)d_in[11];
    float* out = (float*)d_out;

    cudaFuncSetAttribute(seq2seq_gru_kernel,
                         cudaFuncAttributeMaxDynamicSharedMemorySize, SMEM_BYTES);
    seq2seq_gru_kernel<<<NBLK, NTHR, SMEM_BYTES>>>(
        x, xy, eWih, eWhh, ebih, ebhh, dWih, dWhh, dbih, dbhh, Wout, bout, out);
}